// round 1
// baseline (speedup 1.0000x reference)
#include <cuda_runtime.h>
#include <math.h>

#define E_NUM   8
#define D_DIM   1024
#define H_DIM   1024
#define NTOK    2048
#define TOPK    2
#define NPAIR   (NTOK * TOPK)     // 4096

#define TM 128
#define TK 16

// -------- scratch (device globals; no runtime allocation allowed) ----------
__device__ float g_act[(size_t)NPAIR * H_DIM];      // 16 MB: silu(g)*h, indexed by sorted slot
__device__ float g_ypair[(size_t)NPAIR * D_DIM];    // 16 MB: per-pair output, indexed by pair id
__device__ int   g_pairs[NPAIR];                    // pair ids sorted by expert
__device__ int   g_cnt[E_NUM];
__device__ int   g_off[E_NUM];

// ---------------------------------------------------------------------------
// Kernel 0: bucket pairs by expert (single CTA)
// ---------------------------------------------------------------------------
__global__ void bucket_kernel(const int* __restrict__ expert_idxs) {
    __shared__ int scnt[E_NUM];
    __shared__ int soff[E_NUM];
    __shared__ int spos[E_NUM];
    int tid = threadIdx.x;
    if (tid < E_NUM) scnt[tid] = 0;
    __syncthreads();
    for (int i = tid; i < NPAIR; i += blockDim.x)
        atomicAdd(&scnt[expert_idxs[i]], 1);
    __syncthreads();
    if (tid == 0) {
        int s = 0;
        for (int e = 0; e < E_NUM; e++) { soff[e] = s; spos[e] = s; s += scnt[e]; }
    }
    __syncthreads();
    for (int i = tid; i < NPAIR; i += blockDim.x) {
        int e = expert_idxs[i];
        int pos = atomicAdd(&spos[e], 1);
        g_pairs[pos] = i;
    }
    __syncthreads();
    if (tid < E_NUM) { g_cnt[tid] = scnt[tid]; g_off[tid] = soff[tid]; }
}

// ---------------------------------------------------------------------------
// Kernel 1: grouped GEMM1 + fused SiLU-GLU
//   For expert e: act = silu( Xe @ W1[e][:, H:] ) * ( Xe @ W1[e][:, :H] )
//   Tile: 128 rows x (64 h-cols + 64 g-cols). Thread tile 8x(4+4). 256 thr.
//   grid = (H/64, NPAIR/TM, E)
// ---------------------------------------------------------------------------
__global__ void __launch_bounds__(256, 2)
gemm1_glu_kernel(const float* __restrict__ x, const float* __restrict__ W1) {
    const int e   = blockIdx.z;
    const int cnt = g_cnt[e];
    const int m0  = blockIdx.y * TM;
    if (m0 >= cnt) return;
    const int off = g_off[e];
    const int n0  = blockIdx.x * 64;

    const float* __restrict__ B = W1 + (size_t)e * D_DIM * (2 * H_DIM);

    __shared__ float As[TK][TM];
    __shared__ float Bs[TK][TM];   // [k][128]: cols 0..63 = h, 64..127 = g
    __shared__ int   rows_s[TM];

    const int tid = threadIdx.x;
    const int ty  = tid >> 4;      // 0..15, owns rows ty*8..ty*8+7
    const int tx  = tid & 15;      // 0..15, owns h-cols tx*4..+3 and g-cols 64+tx*4..+3

    if (tid < TM) {
        int m = m0 + tid;
        int tok = 0;
        if (m < cnt) tok = g_pairs[off + m] >> 1;
        rows_s[tid] = tok;
    }
    __syncthreads();

    float acc[8][8];
#pragma unroll
    for (int r = 0; r < 8; r++)
#pragma unroll
        for (int c = 0; c < 8; c++) acc[r][c] = 0.f;

    for (int kt = 0; kt < D_DIM; kt += TK) {
        // ---- load A tile (gathered rows), 512 float4 / 256 threads ----
#pragma unroll
        for (int it = 0; it < 2; it++) {
            int q   = tid + it * 256;
            int row = q >> 2;
            int kq  = (q & 3) * 4;
            float4 v = *(const float4*)(x + (size_t)rows_s[row] * D_DIM + kt + kq);
            As[kq + 0][row] = v.x;
            As[kq + 1][row] = v.y;
            As[kq + 2][row] = v.z;
            As[kq + 3][row] = v.w;
        }
        // ---- load B tile: 16 k-rows x 128 cols (64 from each half) ----
#pragma unroll
        for (int it = 0; it < 2; it++) {
            int q  = tid + it * 256;
            int k  = q >> 5;
            int j4 = (q & 31) * 4;
            int gcol = (j4 < 64) ? (n0 + j4) : (H_DIM + n0 + (j4 - 64));
            *(float4*)&Bs[k][j4] =
                *(const float4*)(B + (size_t)(kt + k) * (2 * H_DIM) + gcol);
        }
        __syncthreads();

#pragma unroll
        for (int kk = 0; kk < TK; kk++) {
            float a[8], b[8];
            *(float4*)&a[0] = *(const float4*)&As[kk][ty * 8];
            *(float4*)&a[4] = *(const float4*)&As[kk][ty * 8 + 4];
            *(float4*)&b[0] = *(const float4*)&Bs[kk][tx * 4];        // h
            *(float4*)&b[4] = *(const float4*)&Bs[kk][64 + tx * 4];   // g
#pragma unroll
            for (int r = 0; r < 8; r++)
#pragma unroll
                for (int c = 0; c < 8; c++)
                    acc[r][c] = fmaf(a[r], b[c], acc[r][c]);
        }
        __syncthreads();
    }

    // ---- epilogue: act = silu(g) * h ----
#pragma unroll
    for (int r = 0; r < 8; r++) {
        int m = m0 + ty * 8 + r;
        if (m < cnt) {
            float4 o;
            float g0 = acc[r][4], g1 = acc[r][5], g2 = acc[r][6], g3 = acc[r][7];
            o.x = acc[r][0] * (g0 / (1.f + expf(-g0)));
            o.y = acc[r][1] * (g1 / (1.f + expf(-g1)));
            o.z = acc[r][2] * (g2 / (1.f + expf(-g2)));
            o.w = acc[r][3] * (g3 / (1.f + expf(-g3)));
            *(float4*)(g_act + (size_t)(off + m) * H_DIM + n0 + tx * 4) = o;
        }
    }
}

// ---------------------------------------------------------------------------
// Kernel 2: grouped GEMM2, scale by gate prob, scatter to y_pair by pair id
//   Tile: 128x128, thread tile 8x8, 256 threads.  grid = (D/128, NPAIR/TM, E)
// ---------------------------------------------------------------------------
__global__ void __launch_bounds__(256, 2)
gemm2_kernel(const float* __restrict__ expert_p, const float* __restrict__ W2) {
    const int e   = blockIdx.z;
    const int cnt = g_cnt[e];
    const int m0  = blockIdx.y * TM;
    if (m0 >= cnt) return;
    const int off = g_off[e];
    const int n0  = blockIdx.x * 128;

    const float* __restrict__ B = W2 + (size_t)e * H_DIM * D_DIM;

    __shared__ float As[TK][TM];
    __shared__ float Bs[TK][TM];

    const int tid = threadIdx.x;
    const int ty  = tid >> 4;
    const int tx  = tid & 15;

    float acc[8][8];
#pragma unroll
    for (int r = 0; r < 8; r++)
#pragma unroll
        for (int c = 0; c < 8; c++) acc[r][c] = 0.f;

    for (int kt = 0; kt < H_DIM; kt += TK) {
        // ---- load A tile (contiguous sorted rows of g_act) ----
#pragma unroll
        for (int it = 0; it < 2; it++) {
            int q   = tid + it * 256;
            int row = q >> 2;
            int kq  = (q & 3) * 4;
            int gr  = off + m0 + row;
            if (gr > NPAIR - 1) gr = NPAIR - 1;
            float4 v = *(const float4*)(g_act + (size_t)gr * H_DIM + kt + kq);
            As[kq + 0][row] = v.x;
            As[kq + 1][row] = v.y;
            As[kq + 2][row] = v.z;
            As[kq + 3][row] = v.w;
        }
        // ---- load B tile ----
#pragma unroll
        for (int it = 0; it < 2; it++) {
            int q  = tid + it * 256;
            int k  = q >> 5;
            int j4 = (q & 31) * 4;
            *(float4*)&Bs[k][j4] =
                *(const float4*)(B + (size_t)(kt + k) * D_DIM + n0 + j4);
        }
        __syncthreads();

#pragma unroll
        for (int kk = 0; kk < TK; kk++) {
            float a[8], b[8];
            *(float4*)&a[0] = *(const float4*)&As[kk][ty * 8];
            *(float4*)&a[4] = *(const float4*)&As[kk][ty * 8 + 4];
            *(float4*)&b[0] = *(const float4*)&Bs[kk][tx * 8];
            *(float4*)&b[4] = *(const float4*)&Bs[kk][tx * 8 + 4];
#pragma unroll
            for (int r = 0; r < 8; r++)
#pragma unroll
                for (int c = 0; c < 8; c++)
                    acc[r][c] = fmaf(a[r], b[c], acc[r][c]);
        }
        __syncthreads();
    }

    // ---- epilogue: scale by gate prob, scatter by pair id ----
#pragma unroll
    for (int r = 0; r < 8; r++) {
        int m = m0 + ty * 8 + r;
        if (m < cnt) {
            int   pid = g_pairs[off + m];
            float pv  = expert_p[pid];
            float* dst = g_ypair + (size_t)pid * D_DIM + n0 + tx * 8;
            float4 o1, o2;
            o1.x = acc[r][0] * pv; o1.y = acc[r][1] * pv;
            o1.z = acc[r][2] * pv; o1.w = acc[r][3] * pv;
            o2.x = acc[r][4] * pv; o2.y = acc[r][5] * pv;
            o2.z = acc[r][6] * pv; o2.w = acc[r][7] * pv;
            *(float4*)(dst)     = o1;
            *(float4*)(dst + 4) = o2;
        }
    }
}

// ---------------------------------------------------------------------------
// Kernel 3: combine the K=2 slots of each token
// ---------------------------------------------------------------------------
__global__ void combine_kernel(float* __restrict__ out) {
    const int D4 = D_DIM / 4;
    int q = blockIdx.x * blockDim.x + threadIdx.x;   // float4 index into out
    if (q >= NTOK * D4) return;
    int t  = q / D4;
    int d4 = q - t * D4;
    const float4* yp = (const float4*)g_ypair;
    float4 a = yp[(size_t)(2 * t) * D4 + d4];
    float4 b = yp[(size_t)(2 * t + 1) * D4 + d4];
    float4 o;
    o.x = a.x + b.x; o.y = a.y + b.y; o.z = a.z + b.z; o.w = a.w + b.w;
    ((float4*)out)[q] = o;
}

// ---------------------------------------------------------------------------
extern "C" void kernel_launch(void* const* d_in, const int* in_sizes, int n_in,
                              void* d_out, int out_size) {
    const float* x    = (const float*)d_in[0];  // [B,S,D]
    const float* ep   = (const float*)d_in[1];  // [N,K]
    const int*   eidx = (const int*)  d_in[2];  // [N,K]
    const float* W1   = (const float*)d_in[3];  // [E,D,2H]
    const float* W2   = (const float*)d_in[4];  // [E,H,D]
    float*       out  = (float*)d_out;

    bucket_kernel<<<1, 512>>>(eidx);

    dim3 g1(H_DIM / 64, NPAIR / TM, E_NUM);     // (16, 32, 8)
    gemm1_glu_kernel<<<g1, 256>>>(x, W1);

    dim3 g2(D_DIM / 128, NPAIR / TM, E_NUM);    // (8, 32, 8)
    gemm2_kernel<<<g2, 256>>>(ep, W2);

    int total4 = NTOK * (D_DIM / 4);
    combine_kernel<<<(total4 + 255) / 256, 256>>>(out);
}

// round 4
// speedup vs baseline: 1.8041x; 1.8041x over previous
#include <cuda_runtime.h>
#include <cuda_bf16.h>
#include <cstdint>
#include <math.h>

#define E_NUM 8
#define D_DIM 1024
#define H_DIM 1024
#define H2    2048
#define NTOK  2048
#define NPAIR 4096

// ----------------------------- scratch globals ------------------------------
__device__ int g_pairs[NPAIR];
__device__ int g_cnt[E_NUM];
__device__ int g_off[E_NUM];
__device__ __nv_bfloat16 g_x_hi[(size_t)NTOK * D_DIM];            // by TOKEN
__device__ __nv_bfloat16 g_x_lo[(size_t)NTOK * D_DIM];
__device__ __nv_bfloat16 g_w1t_hi[(size_t)E_NUM * H2 * D_DIM];    // [E][n=2H][k=D]
__device__ __nv_bfloat16 g_w1t_lo[(size_t)E_NUM * H2 * D_DIM];
__device__ __nv_bfloat16 g_w2t_hi[(size_t)E_NUM * D_DIM * H_DIM]; // [E][n=D][k=H]
__device__ __nv_bfloat16 g_w2t_lo[(size_t)E_NUM * D_DIM * H_DIM];
__device__ __nv_bfloat16 g_act_hi[(size_t)NPAIR * H_DIM];         // by sorted SLOT
__device__ __nv_bfloat16 g_act_lo[(size_t)NPAIR * H_DIM];
__device__ float g_ypair[(size_t)NPAIR * D_DIM];                  // by pair id

// ------------------------------ helpers -------------------------------------
__device__ __forceinline__ uint32_t smem_u32(const void* p) {
    uint32_t a;
    asm("{ .reg .u64 t; cvta.to.shared.u64 t, %1; cvt.u32.u64 %0, t; }"
        : "=r"(a) : "l"(p));
    return a;
}
__device__ __forceinline__ void cp16(uint32_t dst, const void* src) {
    asm volatile("cp.async.cg.shared.global [%0], [%1], 16;"
                 :: "r"(dst), "l"(src) : "memory");
}
#define CP_COMMIT() asm volatile("cp.async.commit_group;" ::: "memory")
#define CP_WAIT(n)  asm volatile("cp.async.wait_group %0;" :: "n"(n) : "memory")

__device__ __forceinline__ void ldsm4(uint32_t* r, uint32_t a) {
    asm volatile("ldmatrix.sync.aligned.m8n8.x4.shared.b16 {%0,%1,%2,%3}, [%4];"
                 : "=r"(r[0]), "=r"(r[1]), "=r"(r[2]), "=r"(r[3]) : "r"(a));
}
__device__ __forceinline__ void ldsm2(uint32_t* r, uint32_t a) {
    asm volatile("ldmatrix.sync.aligned.m8n8.x2.shared.b16 {%0,%1}, [%2];"
                 : "=r"(r[0]), "=r"(r[1]) : "r"(a));
}
__device__ __forceinline__ void mma16816(float* d, const uint32_t* a, const uint32_t* b) {
    asm volatile(
        "mma.sync.aligned.m16n8k16.row.col.f32.bf16.bf16.f32 "
        "{%0,%1,%2,%3}, {%4,%5,%6,%7}, {%8,%9}, {%0,%1,%2,%3};"
        : "+f"(d[0]), "+f"(d[1]), "+f"(d[2]), "+f"(d[3])
        : "r"(a[0]), "r"(a[1]), "r"(a[2]), "r"(a[3]), "r"(b[0]), "r"(b[1]));
}
__device__ __forceinline__ uint32_t pack_bf2(__nv_bfloat16 a, __nv_bfloat16 b) {
    return ((uint32_t)__bfloat16_as_ushort(b) << 16) | (uint32_t)__bfloat16_as_ushort(a);
}
__device__ __forceinline__ void split_f32(float v, __nv_bfloat16& hi, __nv_bfloat16& lo) {
    hi = __float2bfloat16_rn(v);
    lo = __float2bfloat16_rn(v - __bfloat162float(hi));
}
__device__ __forceinline__ float silu_mul(float h, float g) {
    return h * (g / (1.f + __expf(-g)));
}

// SMEM layout: rows_s[128] ints @0, stages @512.
// Stage: Ahi(128x80B) | Alo | Bhi | Blo, 40960 B; 2 stages.
#define ROWB     80
#define MAT_SZ   (128 * ROWB)
#define STAGE_SZ (4 * MAT_SZ)
#define SMEM_DYN (512 + 2 * STAGE_SZ)
#define OFF_AHI  0
#define OFF_ALO  MAT_SZ
#define OFF_BHI  (2 * MAT_SZ)
#define OFF_BLO  (3 * MAT_SZ)

// ---------------------------------------------------------------------------
// Kernel 0: bucket pairs by expert (single CTA)
// ---------------------------------------------------------------------------
__global__ void bucket_kernel(const int* __restrict__ expert_idxs) {
    __shared__ int scnt[E_NUM];
    __shared__ int soff[E_NUM];
    __shared__ int spos[E_NUM];
    int tid = threadIdx.x;
    if (tid < E_NUM) scnt[tid] = 0;
    __syncthreads();
    for (int i = tid; i < NPAIR; i += blockDim.x)
        atomicAdd(&scnt[expert_idxs[i]], 1);
    __syncthreads();
    if (tid == 0) {
        int s = 0;
        for (int e = 0; e < E_NUM; e++) { soff[e] = s; spos[e] = s; s += scnt[e]; }
    }
    __syncthreads();
    for (int i = tid; i < NPAIR; i += blockDim.x) {
        int e = expert_idxs[i];
        int pos = atomicAdd(&spos[e], 1);
        g_pairs[pos] = i;
    }
    __syncthreads();
    if (tid < E_NUM) { g_cnt[tid] = scnt[tid]; g_off[tid] = soff[tid]; }
}

// ---------------------------------------------------------------------------
// Kernel 1: convert x by TOKEN to bf16 hi/lo (no gather here; GEMM1 gathers)
// ---------------------------------------------------------------------------
__global__ void conv_x_kernel(const float* __restrict__ x) {
    int tok = blockIdx.x;
    int t   = threadIdx.x;
    float4 v = ((const float4*)(x + (size_t)tok * D_DIM))[t];
    __nv_bfloat16 h0, l0, h1, l1, h2, l2, h3, l3;
    split_f32(v.x, h0, l0); split_f32(v.y, h1, l1);
    split_f32(v.z, h2, l2); split_f32(v.w, h3, l3);
    size_t o = (size_t)tok * D_DIM + t * 4;
    *(uint2*)(g_x_hi + o) = make_uint2(pack_bf2(h0, h1), pack_bf2(h2, h3));
    *(uint2*)(g_x_lo + o) = make_uint2(pack_bf2(l0, l1), pack_bf2(l2, l3));
}

// ---------------------------------------------------------------------------
// Kernel 2a/2b: transpose-convert W1 -> [E,2H,D], W2 -> [E,D,H] bf16 hi/lo
// ---------------------------------------------------------------------------
__global__ void conv_w1t_kernel(const float* __restrict__ W1) {
    __shared__ float tile[32][33];
    int e  = blockIdx.z;
    int n0 = blockIdx.x * 32;
    int d0 = blockIdx.y * 32;
    int tx = threadIdx.x, ty = threadIdx.y;
    const float* src = W1 + (size_t)e * D_DIM * H2;
#pragma unroll
    for (int i = 0; i < 4; i++) {
        int d = d0 + ty + i * 8;
        tile[ty + i * 8][tx] = src[(size_t)d * H2 + n0 + tx];
    }
    __syncthreads();
#pragma unroll
    for (int i = 0; i < 4; i++) {
        int n = n0 + ty + i * 8;
        float v = tile[tx][ty + i * 8];
        __nv_bfloat16 h, l;
        split_f32(v, h, l);
        size_t o = ((size_t)e * H2 + n) * D_DIM + d0 + tx;
        g_w1t_hi[o] = h;
        g_w1t_lo[o] = l;
    }
}

__global__ void conv_w2t_kernel(const float* __restrict__ W2) {
    __shared__ float tile[32][33];
    int e  = blockIdx.z;
    int d0 = blockIdx.x * 32;
    int h0 = blockIdx.y * 32;
    int tx = threadIdx.x, ty = threadIdx.y;
    const float* src = W2 + (size_t)e * H_DIM * D_DIM;
#pragma unroll
    for (int i = 0; i < 4; i++) {
        int h = h0 + ty + i * 8;
        tile[ty + i * 8][tx] = src[(size_t)h * D_DIM + d0 + tx];
    }
    __syncthreads();
#pragma unroll
    for (int i = 0; i < 4; i++) {
        int d = d0 + ty + i * 8;
        float v = tile[tx][ty + i * 8];
        __nv_bfloat16 h, l;
        split_f32(v, h, l);
        size_t o = ((size_t)e * D_DIM + d) * H_DIM + h0 + tx;
        g_w2t_hi[o] = h;
        g_w2t_lo[o] = l;
    }
}

// ---------------------------------------------------------------------------
// GEMM1 (mma.sync bf16 hi/lo): act = h * silu(g), fused in registers
//   CTA 128 rows x (64 h-cols + 64 g-cols). 8 warps, warp = 32m x 64c
//   (c = 32 matching h + 32 matching g).  grid = (H/64, NPAIR/128, E)
// ---------------------------------------------------------------------------
__global__ void __launch_bounds__(256, 1) gemm1_mma() {
    extern __shared__ char smem[];
    const int e   = blockIdx.z;
    const int bn  = blockIdx.x;
    const int bm  = blockIdx.y;
    const int cnt = g_cnt[e];
    if (bm * 128 >= cnt) return;
    const int off = g_off[e];
    const int tid = threadIdx.x;
    const int wid = tid >> 5;
    const int l   = tid & 31;
    const int wm  = wid >> 1;    // 0..3: m-group (32 rows each)
    const int wc  = wid & 1;     // 0..1: c-group (32 h + 32 g)

    int* rows_s = (int*)smem;
    const uint32_t sbase = smem_u32(smem) + 512;

    if (tid < 128) {
        int m = bm * 128 + tid;
        rows_s[tid] = (m < cnt) ? (g_pairs[off + m] >> 1) : 0;
    }
    __syncthreads();

    // per-thread ldmatrix offsets (relative to matrix base within a stage)
    uint32_t a_rel[2][2], b_rel[8][2];
#pragma unroll
    for (int mt = 0; mt < 2; mt++)
#pragma unroll
        for (int kk = 0; kk < 2; kk++)
            a_rel[mt][kk] = (wm * 32 + mt * 16 + (l & 15)) * ROWB + kk * 32 + (l >> 4) * 16;
#pragma unroll
    for (int nt = 0; nt < 8; nt++) {
        int brow = (nt < 4) ? (wc * 32 + nt * 8) : (64 + wc * 32 + (nt - 4) * 8);
#pragma unroll
        for (int kk = 0; kk < 2; kk++)
            b_rel[nt][kk] = (brow + (l & 7)) * ROWB + kk * 32 + ((l >> 3) & 1) * 16;
    }

    float acc[2][8][4];
#pragma unroll
    for (int mt = 0; mt < 2; mt++)
#pragma unroll
        for (int nt = 0; nt < 8; nt++)
#pragma unroll
            for (int i = 0; i < 4; i++) acc[mt][nt][i] = 0.f;

    // ---- stage loader: gather A rows by token id, stream B rows ----
    auto load_stage = [&](int c, int buf) {
        const int kt = c * 32;
        const uint32_t st = sbase + buf * STAGE_SZ;
#pragma unroll
        for (int i = 0; i < 4; i++) {
            int q = tid + i * 256;
            if (q < 512) {
                int r = q >> 2, ch = q & 3;
                size_t gsrc = (size_t)rows_s[r] * D_DIM + kt + ch * 8;
                uint32_t d = st + r * ROWB + ch * 16;
                cp16(d + OFF_AHI, g_x_hi + gsrc);
                cp16(d + OFF_ALO, g_x_lo + gsrc);
            } else {
                int qb = q - 512;
                int r = qb >> 2, ch = qb & 3;
                int ng = (r < 64) ? (bn * 64 + r) : (H_DIM + bn * 64 + (r - 64));
                size_t gsrc = ((size_t)e * H2 + ng) * D_DIM + kt + ch * 8;
                uint32_t d = st + r * ROWB + ch * 16;
                cp16(d + OFF_BHI, g_w1t_hi + gsrc);
                cp16(d + OFF_BLO, g_w1t_lo + gsrc);
            }
        }
        CP_COMMIT();
    };

    load_stage(0, 0);

    for (int c = 0; c < 32; c++) {
        const int buf = c & 1;
        if (c < 31) { load_stage(c + 1, buf ^ 1); CP_WAIT(1); }
        else        { CP_WAIT(0); }
        __syncthreads();
        const uint32_t st = sbase + buf * STAGE_SZ;
#pragma unroll
        for (int kk = 0; kk < 2; kk++) {
            uint32_t ah[2][4], al[2][4], bh[8][2], bl[8][2];
#pragma unroll
            for (int mt = 0; mt < 2; mt++) {
                ldsm4(ah[mt], st + OFF_AHI + a_rel[mt][kk]);
                ldsm4(al[mt], st + OFF_ALO + a_rel[mt][kk]);
            }
#pragma unroll
            for (int nt = 0; nt < 8; nt++) {
                ldsm2(bh[nt], st + OFF_BHI + b_rel[nt][kk]);
                ldsm2(bl[nt], st + OFF_BLO + b_rel[nt][kk]);
            }
#pragma unroll
            for (int mt = 0; mt < 2; mt++)
#pragma unroll
                for (int nt = 0; nt < 8; nt++) {
                    mma16816(acc[mt][nt], ah[mt], bh[nt]);
                    mma16816(acc[mt][nt], al[mt], bh[nt]);
                    mma16816(acc[mt][nt], ah[mt], bl[nt]);
                }
        }
        __syncthreads();
    }

    // ---- epilogue: pair h (nt) with g (nt+4), fuse SiLU-GLU, split, store ----
#pragma unroll
    for (int mt = 0; mt < 2; mt++) {
        int m0 = bm * 128 + wm * 32 + mt * 16 + (l >> 2);
        int m1 = m0 + 8;
        bool v0 = (m0 < cnt), v1 = (m1 < cnt);
        size_t row0 = (size_t)(off + m0) * H_DIM;
        size_t row1 = (size_t)(off + m1) * H_DIM;
#pragma unroll
        for (int nt = 0; nt < 4; nt++) {
            int col = bn * 64 + wc * 32 + nt * 8 + 2 * (l & 3);
            float a0 = silu_mul(acc[mt][nt][0], acc[mt][nt + 4][0]);
            float a1 = silu_mul(acc[mt][nt][1], acc[mt][nt + 4][1]);
            float a2 = silu_mul(acc[mt][nt][2], acc[mt][nt + 4][2]);
            float a3 = silu_mul(acc[mt][nt][3], acc[mt][nt + 4][3]);
            __nv_bfloat16 h0, l0, h1, l1, h2, l2, h3, l3;
            split_f32(a0, h0, l0); split_f32(a1, h1, l1);
            split_f32(a2, h2, l2); split_f32(a3, h3, l3);
            if (v0) {
                *(uint32_t*)(g_act_hi + row0 + col) = pack_bf2(h0, h1);
                *(uint32_t*)(g_act_lo + row0 + col) = pack_bf2(l0, l1);
            }
            if (v1) {
                *(uint32_t*)(g_act_hi + row1 + col) = pack_bf2(h2, h3);
                *(uint32_t*)(g_act_lo + row1 + col) = pack_bf2(l2, l3);
            }
        }
    }
}

// ---------------------------------------------------------------------------
// GEMM2 (mma.sync bf16 hi/lo): y_pair = (act @ W2t) * p, scatter by pair id
//   CTA 128 x 128, warp 32m x 64n.  grid = (D/128, NPAIR/128, E)
// ---------------------------------------------------------------------------
__global__ void __launch_bounds__(256, 1) gemm2_mma(const float* __restrict__ expert_p) {
    extern __shared__ char smem[];
    const int e   = blockIdx.z;
    const int bn  = blockIdx.x;
    const int bm  = blockIdx.y;
    const int cnt = g_cnt[e];
    if (bm * 128 >= cnt) return;
    const int off = g_off[e];
    const int tid = threadIdx.x;
    const int wid = tid >> 5;
    const int l   = tid & 31;
    const int wm  = wid >> 1;
    const int wc  = wid & 1;

    const uint32_t sbase = smem_u32(smem) + 512;

    uint32_t a_rel[2][2], b_rel[8][2];
#pragma unroll
    for (int mt = 0; mt < 2; mt++)
#pragma unroll
        for (int kk = 0; kk < 2; kk++)
            a_rel[mt][kk] = (wm * 32 + mt * 16 + (l & 15)) * ROWB + kk * 32 + (l >> 4) * 16;
#pragma unroll
    for (int nt = 0; nt < 8; nt++)
#pragma unroll
        for (int kk = 0; kk < 2; kk++)
            b_rel[nt][kk] = (wc * 64 + nt * 8 + (l & 7)) * ROWB + kk * 32 + ((l >> 3) & 1) * 16;

    float acc[2][8][4];
#pragma unroll
    for (int mt = 0; mt < 2; mt++)
#pragma unroll
        for (int nt = 0; nt < 8; nt++)
#pragma unroll
            for (int i = 0; i < 4; i++) acc[mt][nt][i] = 0.f;

    auto load_stage = [&](int c, int buf) {
        const int kt = c * 32;
        const uint32_t st = sbase + buf * STAGE_SZ;
#pragma unroll
        for (int i = 0; i < 4; i++) {
            int q = tid + i * 256;
            if (q < 512) {
                int r = q >> 2, ch = q & 3;
                int gr = off + bm * 128 + r;
                if (gr > NPAIR - 1) gr = NPAIR - 1;
                size_t gsrc = (size_t)gr * H_DIM + kt + ch * 8;
                uint32_t d = st + r * ROWB + ch * 16;
                cp16(d + OFF_AHI, g_act_hi + gsrc);
                cp16(d + OFF_ALO, g_act_lo + gsrc);
            } else {
                int qb = q - 512;
                int r = qb >> 2, ch = qb & 3;
                int ng = bn * 128 + r;
                size_t gsrc = ((size_t)e * D_DIM + ng) * H_DIM + kt + ch * 8;
                uint32_t d = st + r * ROWB + ch * 16;
                cp16(d + OFF_BHI, g_w2t_hi + gsrc);
                cp16(d + OFF_BLO, g_w2t_lo + gsrc);
            }
        }
        CP_COMMIT();
    };

    load_stage(0, 0);

    for (int c = 0; c < 32; c++) {
        const int buf = c & 1;
        if (c < 31) { load_stage(c + 1, buf ^ 1); CP_WAIT(1); }
        else        { CP_WAIT(0); }
        __syncthreads();
        const uint32_t st = sbase + buf * STAGE_SZ;
#pragma unroll
        for (int kk = 0; kk < 2; kk++) {
            uint32_t ah[2][4], al[2][4], bh[8][2], bl[8][2];
#pragma unroll
            for (int mt = 0; mt < 2; mt++) {
                ldsm4(ah[mt], st + OFF_AHI + a_rel[mt][kk]);
                ldsm4(al[mt], st + OFF_ALO + a_rel[mt][kk]);
            }
#pragma unroll
            for (int nt = 0; nt < 8; nt++) {
                ldsm2(bh[nt], st + OFF_BHI + b_rel[nt][kk]);
                ldsm2(bl[nt], st + OFF_BLO + b_rel[nt][kk]);
            }
#pragma unroll
            for (int mt = 0; mt < 2; mt++)
#pragma unroll
                for (int nt = 0; nt < 8; nt++) {
                    mma16816(acc[mt][nt], ah[mt], bh[nt]);
                    mma16816(acc[mt][nt], al[mt], bh[nt]);
                    mma16816(acc[mt][nt], ah[mt], bl[nt]);
                }
        }
        __syncthreads();
    }

    // ---- epilogue: scale by gate prob, scatter rows by pair id ----
#pragma unroll
    for (int mt = 0; mt < 2; mt++) {
        int m0 = bm * 128 + wm * 32 + mt * 16 + (l >> 2);
        int m1 = m0 + 8;
        bool v0 = (m0 < cnt), v1 = (m1 < cnt);
        int   pid0 = 0, pid1 = 0;
        float pv0 = 0.f, pv1 = 0.f;
        if (v0) { pid0 = g_pairs[off + m0]; pv0 = expert_p[pid0]; }
        if (v1) { pid1 = g_pairs[off + m1]; pv1 = expert_p[pid1]; }
        float* dst0 = g_ypair + (size_t)pid0 * D_DIM;
        float* dst1 = g_ypair + (size_t)pid1 * D_DIM;
#pragma unroll
        for (int nt = 0; nt < 8; nt++) {
            int col = bn * 128 + wc * 64 + nt * 8 + 2 * (l & 3);
            if (v0) {
                float2 o = make_float2(acc[mt][nt][0] * pv0, acc[mt][nt][1] * pv0);
                *(float2*)(dst0 + col) = o;
            }
            if (v1) {
                float2 o = make_float2(acc[mt][nt][2] * pv1, acc[mt][nt][3] * pv1);
                *(float2*)(dst1 + col) = o;
            }
        }
    }
}

// ---------------------------------------------------------------------------
// Kernel 5: combine the K=2 slots of each token
// ---------------------------------------------------------------------------
__global__ void combine_kernel(float* __restrict__ out) {
    const int D4 = D_DIM / 4;
    int q = blockIdx.x * blockDim.x + threadIdx.x;
    if (q >= NTOK * D4) return;
    int t  = q / D4;
    int d4 = q - t * D4;
    const float4* yp = (const float4*)g_ypair;
    float4 a = yp[(size_t)(2 * t) * D4 + d4];
    float4 b = yp[(size_t)(2 * t + 1) * D4 + d4];
    float4 o;
    o.x = a.x + b.x; o.y = a.y + b.y; o.z = a.z + b.z; o.w = a.w + b.w;
    ((float4*)out)[q] = o;
}

// ---------------------------------------------------------------------------
extern "C" void kernel_launch(void* const* d_in, const int* in_sizes, int n_in,
                              void* d_out, int out_size) {
    const float* x    = (const float*)d_in[0];
    const float* ep   = (const float*)d_in[1];
    const int*   eidx = (const int*)  d_in[2];
    const float* W1   = (const float*)d_in[3];
    const float* W2   = (const float*)d_in[4];
    float*       out  = (float*)d_out;

    cudaFuncSetAttribute(gemm1_mma, cudaFuncAttributeMaxDynamicSharedMemorySize, SMEM_DYN);
    cudaFuncSetAttribute(gemm2_mma, cudaFuncAttributeMaxDynamicSharedMemorySize, SMEM_DYN);

    bucket_kernel<<<1, 512>>>(eidx);
    conv_x_kernel<<<NTOK, 256>>>(x);

    dim3 cw1(H2 / 32, D_DIM / 32, E_NUM);
    conv_w1t_kernel<<<cw1, dim3(32, 8)>>>(W1);
    dim3 cw2(D_DIM / 32, H_DIM / 32, E_NUM);
    conv_w2t_kernel<<<cw2, dim3(32, 8)>>>(W2);

    dim3 g1(H_DIM / 64, NPAIR / 128, E_NUM);    // (16, 32, 8)
    gemm1_mma<<<g1, 256, SMEM_DYN>>>();

    dim3 g2(D_DIM / 128, NPAIR / 128, E_NUM);   // (8, 32, 8)
    gemm2_mma<<<g2, 256, SMEM_DYN>>>(ep);

    int total4 = NTOK * (D_DIM / 4);
    combine_kernel<<<(total4 + 255) / 256, 256>>>(out);
}

// round 6
// speedup vs baseline: 2.4222x; 1.3426x over previous
#include <cuda_runtime.h>
#include <cuda_fp16.h>
#include <cstdint>
#include <math.h>

#define E_NUM 8
#define D_DIM 1024
#define H_DIM 1024
#define H2    2048
#define NTOK  2048
#define NPAIR 4096

// ----------------------------- scratch globals ------------------------------
__device__ int g_pairs[NPAIR];
__device__ int g_cnt[E_NUM];
__device__ int g_off[E_NUM];
__device__ __half g_x_hi[(size_t)NTOK * D_DIM];             // by TOKEN
__device__ __half g_x_lo[(size_t)NTOK * D_DIM];
__device__ __half g_w1_hi[(size_t)E_NUM * D_DIM * H2];      // [E][k=D][n=2H] (as stored)
__device__ __half g_w2_hi[(size_t)E_NUM * H_DIM * D_DIM];   // [E][k=H][n=D]
__device__ __half g_act_hi[(size_t)NPAIR * H_DIM];          // by sorted SLOT
__device__ __half g_act_lo[(size_t)NPAIR * H_DIM];
__device__ float g_ypair[(size_t)NPAIR * D_DIM];            // by pair id

// ------------------------------ helpers -------------------------------------
__device__ __forceinline__ uint32_t smem_u32(const void* p) {
    uint32_t a;
    asm("{ .reg .u64 t; cvta.to.shared.u64 t, %1; cvt.u32.u64 %0, t; }"
        : "=r"(a) : "l"(p));
    return a;
}
__device__ __forceinline__ void cp16(uint32_t dst, const void* src) {
    asm volatile("cp.async.cg.shared.global [%0], [%1], 16;"
                 :: "r"(dst), "l"(src) : "memory");
}
#define CP_COMMIT() asm volatile("cp.async.commit_group;" ::: "memory")
#define CP_WAIT(n)  asm volatile("cp.async.wait_group %0;" :: "n"(n) : "memory")

__device__ __forceinline__ void ldsm4(uint32_t* r, uint32_t a) {
    asm volatile("ldmatrix.sync.aligned.m8n8.x4.shared.b16 {%0,%1,%2,%3}, [%4];"
                 : "=r"(r[0]), "=r"(r[1]), "=r"(r[2]), "=r"(r[3]) : "r"(a));
}
__device__ __forceinline__ void ldsm4t(uint32_t* r, uint32_t a) {
    asm volatile("ldmatrix.sync.aligned.m8n8.x4.trans.shared.b16 {%0,%1,%2,%3}, [%4];"
                 : "=r"(r[0]), "=r"(r[1]), "=r"(r[2]), "=r"(r[3]) : "r"(a));
}
__device__ __forceinline__ void mma16816(float* d, const uint32_t* a, const uint32_t* b) {
    asm volatile(
        "mma.sync.aligned.m16n8k16.row.col.f32.f16.f16.f32 "
        "{%0,%1,%2,%3}, {%4,%5,%6,%7}, {%8,%9}, {%0,%1,%2,%3};"
        : "+f"(d[0]), "+f"(d[1]), "+f"(d[2]), "+f"(d[3])
        : "r"(a[0]), "r"(a[1]), "r"(a[2]), "r"(a[3]), "r"(b[0]), "r"(b[1]));
}
__device__ __forceinline__ uint32_t pack_h2(__half a, __half b) {
    return ((uint32_t)__half_as_ushort(b) << 16) | (uint32_t)__half_as_ushort(a);
}
__device__ __forceinline__ void split_f32h(float v, __half& hi, __half& lo) {
    hi = __float2half_rn(v);
    lo = __float2half_rn(v - __half2float(hi));
}
__device__ __forceinline__ float silu_mul(float h, float g) {
    return h * (g / (1.f + __expf(-g)));
}

// SMEM: rows_s[128] ints @0; stages @512.
// Stage: Ahi [128m][32k] pitch 80 | Alo same | B [32k][128n] pitch 272.
#define A_PITCH  80
#define B_PITCH  272
#define OFF_AHI  0
#define OFF_ALO  (128 * A_PITCH)
#define OFF_B    (2 * 128 * A_PITCH)
#define STAGE_SZ (2 * 128 * A_PITCH + 32 * B_PITCH)   // 29184
#define SMEM_DYN (512 + 2 * STAGE_SZ)

// ---------------------------------------------------------------------------
// Kernel 0: bucket pairs by expert (single CTA)
// ---------------------------------------------------------------------------
__global__ void bucket_kernel(const int* __restrict__ expert_idxs) {
    __shared__ int scnt[E_NUM];
    __shared__ int soff[E_NUM];
    __shared__ int spos[E_NUM];
    int tid = threadIdx.x;
    if (tid < E_NUM) scnt[tid] = 0;
    __syncthreads();
    for (int i = tid; i < NPAIR; i += blockDim.x)
        atomicAdd(&scnt[expert_idxs[i]], 1);
    __syncthreads();
    if (tid == 0) {
        int s = 0;
        for (int e = 0; e < E_NUM; e++) { soff[e] = s; spos[e] = s; s += scnt[e]; }
    }
    __syncthreads();
    for (int i = tid; i < NPAIR; i += blockDim.x) {
        int e = expert_idxs[i];
        int pos = atomicAdd(&spos[e], 1);
        g_pairs[pos] = i;
    }
    __syncthreads();
    if (tid < E_NUM) { g_cnt[tid] = scnt[tid]; g_off[tid] = soff[tid]; }
}

// ---------------------------------------------------------------------------
// Kernel 1: convert x by TOKEN to fp16 hi/lo
// ---------------------------------------------------------------------------
__global__ void conv_x_kernel(const float* __restrict__ x) {
    int tok = blockIdx.x;
    int t   = threadIdx.x;
    float4 v = ((const float4*)(x + (size_t)tok * D_DIM))[t];
    __half h0, l0, h1, l1, h2, l2, h3, l3;
    split_f32h(v.x, h0, l0); split_f32h(v.y, h1, l1);
    split_f32h(v.z, h2, l2); split_f32h(v.w, h3, l3);
    size_t o = (size_t)tok * D_DIM + t * 4;
    *(uint2*)(g_x_hi + o) = make_uint2(pack_h2(h0, h1), pack_h2(h2, h3));
    *(uint2*)(g_x_lo + o) = make_uint2(pack_h2(l0, l1), pack_h2(l2, l3));
}

// ---------------------------------------------------------------------------
// Kernel 2a/2b: streaming convert W1/W2 fp32 -> fp16 hi (device globals
// referenced IN DEVICE CODE — host may not take a __device__ symbol's address)
// ---------------------------------------------------------------------------
__global__ void conv_w1_kernel(const float* __restrict__ W1) {
    const int total4 = E_NUM * D_DIM * H2 / 4;
    int idx = blockIdx.x * blockDim.x + threadIdx.x;
    if (idx >= total4) return;
    float4 v = ((const float4*)W1)[idx];
    uint2 o;
    o.x = pack_h2(__float2half_rn(v.x), __float2half_rn(v.y));
    o.y = pack_h2(__float2half_rn(v.z), __float2half_rn(v.w));
    *(uint2*)(g_w1_hi + (size_t)idx * 4) = o;
}

__global__ void conv_w2_kernel(const float* __restrict__ W2) {
    const int total4 = E_NUM * H_DIM * D_DIM / 4;
    int idx = blockIdx.x * blockDim.x + threadIdx.x;
    if (idx >= total4) return;
    float4 v = ((const float4*)W2)[idx];
    uint2 o;
    o.x = pack_h2(__float2half_rn(v.x), __float2half_rn(v.y));
    o.y = pack_h2(__float2half_rn(v.z), __float2half_rn(v.w));
    *(uint2*)(g_w2_hi + (size_t)idx * 4) = o;
}

// ---------------------------------------------------------------------------
// GEMM1 (mma.sync fp16, 2-term A-split): act = h * silu(g)
//   CTA 128 rows x (64 h + 64 g cols). 8 warps = wm(4) x wc(2); warp 32m x 64c.
//   B loaded from k-major W1 via ldmatrix.trans.   grid = (H/64, NPAIR/128, E)
// ---------------------------------------------------------------------------
__global__ void __launch_bounds__(256, 1) gemm1_mma() {
    extern __shared__ char smem[];
    const int e   = blockIdx.z;
    const int bn  = blockIdx.x;
    const int bm  = blockIdx.y;
    const int cnt = g_cnt[e];
    if (bm * 128 >= cnt) return;
    const int off = g_off[e];
    const int tid = threadIdx.x;
    const int wid = tid >> 5;
    const int l   = tid & 31;
    const int wm  = wid >> 1;
    const int wc  = wid & 1;

    int* rows_s = (int*)smem;
    const uint32_t sbase = smem_u32(smem) + 512;

    if (tid < 128) {
        int m = bm * 128 + tid;
        rows_s[tid] = (m < cnt) ? (g_pairs[off + m] >> 1) : 0;
    }
    __syncthreads();

    // A ldsm (row-major): lanes 0-15 rows, 16-31 col+16
    uint32_t a_rel[2][2];
#pragma unroll
    for (int mt = 0; mt < 2; mt++)
#pragma unroll
        for (int kk = 0; kk < 2; kk++)
            a_rel[mt][kk] = (wm * 32 + mt * 16 + (l & 15)) * A_PITCH + kk * 32 + (l >> 4) * 16;

    // B ldsm4.trans: p=0,1 -> h-region col pairs; p=2,3 -> g-region
    uint32_t b_rel[4][2];
#pragma unroll
    for (int p = 0; p < 4; p++) {
        int colbase = (p < 2) ? (wc * 32 + p * 16) : (64 + wc * 32 + (p - 2) * 16);
#pragma unroll
        for (int kk = 0; kk < 2; kk++)
            b_rel[p][kk] = (kk * 16 + (l & 15)) * B_PITCH + (colbase + (l >> 4) * 8) * 2;
    }

    float acc[2][8][4];
#pragma unroll
    for (int mt = 0; mt < 2; mt++)
#pragma unroll
        for (int nt = 0; nt < 8; nt++)
#pragma unroll
            for (int i = 0; i < 4; i++) acc[mt][nt][i] = 0.f;

    auto load_stage = [&](int c, int buf) {
        const int kt = c * 32;
        const uint32_t st = sbase + buf * STAGE_SZ;
        // A hi: 512 chunks
#pragma unroll
        for (int i = 0; i < 2; i++) {
            int q = tid + i * 256;
            int r = q >> 2, ch = q & 3;
            cp16(st + OFF_AHI + r * A_PITCH + ch * 16,
                 g_x_hi + (size_t)rows_s[r] * D_DIM + kt + ch * 8);
        }
        // A lo: 512 chunks
#pragma unroll
        for (int i = 0; i < 2; i++) {
            int q = tid + i * 256;
            int r = q >> 2, ch = q & 3;
            cp16(st + OFF_ALO + r * A_PITCH + ch * 16,
                 g_x_lo + (size_t)rows_s[r] * D_DIM + kt + ch * 8);
        }
        // B: 512 chunks, [32k][128n]; cols 0-63 = h @ bn*64, 64-127 = g @ H+bn*64
#pragma unroll
        for (int i = 0; i < 2; i++) {
            int q = tid + i * 256;
            int r = q >> 4, ch = q & 15;
            int gcol = (ch < 8) ? (bn * 64 + ch * 8) : (H_DIM + bn * 64 + (ch - 8) * 8);
            cp16(st + OFF_B + r * B_PITCH + ch * 16,
                 g_w1_hi + ((size_t)e * D_DIM + kt + r) * H2 + gcol);
        }
        CP_COMMIT();
    };

    load_stage(0, 0);

    for (int c = 0; c < 32; c++) {
        const int buf = c & 1;
        if (c < 31) { load_stage(c + 1, buf ^ 1); CP_WAIT(1); }
        else        { CP_WAIT(0); }
        __syncthreads();
        const uint32_t st = sbase + buf * STAGE_SZ;
#pragma unroll
        for (int kk = 0; kk < 2; kk++) {
            uint32_t ah[2][4], al[2][4], bf[4][4];
#pragma unroll
            for (int mt = 0; mt < 2; mt++) {
                ldsm4(ah[mt], st + OFF_AHI + a_rel[mt][kk]);
                ldsm4(al[mt], st + OFF_ALO + a_rel[mt][kk]);
            }
#pragma unroll
            for (int p = 0; p < 4; p++)
                ldsm4t(bf[p], st + OFF_B + b_rel[p][kk]);
#pragma unroll
            for (int mt = 0; mt < 2; mt++)
#pragma unroll
                for (int nt = 0; nt < 8; nt++) {
                    const uint32_t* b = &bf[nt >> 1][(nt & 1) * 2];
                    mma16816(acc[mt][nt], ah[mt], b);
                    mma16816(acc[mt][nt], al[mt], b);
                }
        }
        __syncthreads();
    }

    // ---- epilogue: pair h (nt) with g (nt+4), SiLU-GLU, fp16 split, store ----
#pragma unroll
    for (int mt = 0; mt < 2; mt++) {
        int m0 = bm * 128 + wm * 32 + mt * 16 + (l >> 2);
        int m1 = m0 + 8;
        bool v0 = (m0 < cnt), v1 = (m1 < cnt);
        size_t row0 = (size_t)(off + m0) * H_DIM;
        size_t row1 = (size_t)(off + m1) * H_DIM;
#pragma unroll
        for (int nt = 0; nt < 4; nt++) {
            int col = bn * 64 + wc * 32 + nt * 8 + 2 * (l & 3);
            float a0 = silu_mul(acc[mt][nt][0], acc[mt][nt + 4][0]);
            float a1 = silu_mul(acc[mt][nt][1], acc[mt][nt + 4][1]);
            float a2 = silu_mul(acc[mt][nt][2], acc[mt][nt + 4][2]);
            float a3 = silu_mul(acc[mt][nt][3], acc[mt][nt + 4][3]);
            __half h0, l0, h1, l1, h2, l2, h3, l3;
            split_f32h(a0, h0, l0); split_f32h(a1, h1, l1);
            split_f32h(a2, h2, l2); split_f32h(a3, h3, l3);
            if (v0) {
                *(uint32_t*)(g_act_hi + row0 + col) = pack_h2(h0, h1);
                *(uint32_t*)(g_act_lo + row0 + col) = pack_h2(l0, l1);
            }
            if (v1) {
                *(uint32_t*)(g_act_hi + row1 + col) = pack_h2(h2, h3);
                *(uint32_t*)(g_act_lo + row1 + col) = pack_h2(l2, l3);
            }
        }
    }
}

// ---------------------------------------------------------------------------
// GEMM2 (mma.sync fp16, 2-term A-split): y_pair = (act @ W2) * p, scatter
//   CTA 128 x 128, warp 32m x 64n.  grid = (D/128, NPAIR/128, E)
// ---------------------------------------------------------------------------
__global__ void __launch_bounds__(256, 1) gemm2_mma(const float* __restrict__ expert_p) {
    extern __shared__ char smem[];
    const int e   = blockIdx.z;
    const int bn  = blockIdx.x;
    const int bm  = blockIdx.y;
    const int cnt = g_cnt[e];
    if (bm * 128 >= cnt) return;
    const int off = g_off[e];
    const int tid = threadIdx.x;
    const int wid = tid >> 5;
    const int l   = tid & 31;
    const int wm  = wid >> 1;
    const int wc  = wid & 1;

    const uint32_t sbase = smem_u32(smem) + 512;

    uint32_t a_rel[2][2], b_rel[4][2];
#pragma unroll
    for (int mt = 0; mt < 2; mt++)
#pragma unroll
        for (int kk = 0; kk < 2; kk++)
            a_rel[mt][kk] = (wm * 32 + mt * 16 + (l & 15)) * A_PITCH + kk * 32 + (l >> 4) * 16;
#pragma unroll
    for (int p = 0; p < 4; p++) {
        int colbase = wc * 64 + p * 16;
#pragma unroll
        for (int kk = 0; kk < 2; kk++)
            b_rel[p][kk] = (kk * 16 + (l & 15)) * B_PITCH + (colbase + (l >> 4) * 8) * 2;
    }

    float acc[2][8][4];
#pragma unroll
    for (int mt = 0; mt < 2; mt++)
#pragma unroll
        for (int nt = 0; nt < 8; nt++)
#pragma unroll
            for (int i = 0; i < 4; i++) acc[mt][nt][i] = 0.f;

    auto load_stage = [&](int c, int buf) {
        const int kt = c * 32;
        const uint32_t st = sbase + buf * STAGE_SZ;
#pragma unroll
        for (int i = 0; i < 2; i++) {
            int q = tid + i * 256;
            int r = q >> 2, ch = q & 3;
            int gr = off + bm * 128 + r;
            if (gr > NPAIR - 1) gr = NPAIR - 1;
            cp16(st + OFF_AHI + r * A_PITCH + ch * 16,
                 g_act_hi + (size_t)gr * H_DIM + kt + ch * 8);
        }
#pragma unroll
        for (int i = 0; i < 2; i++) {
            int q = tid + i * 256;
            int r = q >> 2, ch = q & 3;
            int gr = off + bm * 128 + r;
            if (gr > NPAIR - 1) gr = NPAIR - 1;
            cp16(st + OFF_ALO + r * A_PITCH + ch * 16,
                 g_act_lo + (size_t)gr * H_DIM + kt + ch * 8);
        }
#pragma unroll
        for (int i = 0; i < 2; i++) {
            int q = tid + i * 256;
            int r = q >> 4, ch = q & 15;
            cp16(st + OFF_B + r * B_PITCH + ch * 16,
                 g_w2_hi + ((size_t)e * H_DIM + kt + r) * D_DIM + bn * 128 + ch * 8);
        }
        CP_COMMIT();
    };

    load_stage(0, 0);

    for (int c = 0; c < 32; c++) {
        const int buf = c & 1;
        if (c < 31) { load_stage(c + 1, buf ^ 1); CP_WAIT(1); }
        else        { CP_WAIT(0); }
        __syncthreads();
        const uint32_t st = sbase + buf * STAGE_SZ;
#pragma unroll
        for (int kk = 0; kk < 2; kk++) {
            uint32_t ah[2][4], al[2][4], bf[4][4];
#pragma unroll
            for (int mt = 0; mt < 2; mt++) {
                ldsm4(ah[mt], st + OFF_AHI + a_rel[mt][kk]);
                ldsm4(al[mt], st + OFF_ALO + a_rel[mt][kk]);
            }
#pragma unroll
            for (int p = 0; p < 4; p++)
                ldsm4t(bf[p], st + OFF_B + b_rel[p][kk]);
#pragma unroll
            for (int mt = 0; mt < 2; mt++)
#pragma unroll
                for (int nt = 0; nt < 8; nt++) {
                    const uint32_t* b = &bf[nt >> 1][(nt & 1) * 2];
                    mma16816(acc[mt][nt], ah[mt], b);
                    mma16816(acc[mt][nt], al[mt], b);
                }
        }
        __syncthreads();
    }

    // ---- epilogue: scale by gate prob, scatter rows by pair id ----
#pragma unroll
    for (int mt = 0; mt < 2; mt++) {
        int m0 = bm * 128 + wm * 32 + mt * 16 + (l >> 2);
        int m1 = m0 + 8;
        bool v0 = (m0 < cnt), v1 = (m1 < cnt);
        int   pid0 = 0, pid1 = 0;
        float pv0 = 0.f, pv1 = 0.f;
        if (v0) { pid0 = g_pairs[off + m0]; pv0 = expert_p[pid0]; }
        if (v1) { pid1 = g_pairs[off + m1]; pv1 = expert_p[pid1]; }
        float* dst0 = g_ypair + (size_t)pid0 * D_DIM;
        float* dst1 = g_ypair + (size_t)pid1 * D_DIM;
#pragma unroll
        for (int nt = 0; nt < 8; nt++) {
            int col = bn * 128 + wc * 64 + nt * 8 + 2 * (l & 3);
            if (v0) {
                float2 o = make_float2(acc[mt][nt][0] * pv0, acc[mt][nt][1] * pv0);
                *(float2*)(dst0 + col) = o;
            }
            if (v1) {
                float2 o = make_float2(acc[mt][nt][2] * pv1, acc[mt][nt][3] * pv1);
                *(float2*)(dst1 + col) = o;
            }
        }
    }
}

// ---------------------------------------------------------------------------
// Kernel 5: combine the K=2 slots of each token
// ---------------------------------------------------------------------------
__global__ void combine_kernel(float* __restrict__ out) {
    const int D4 = D_DIM / 4;
    int q = blockIdx.x * blockDim.x + threadIdx.x;
    if (q >= NTOK * D4) return;
    int t  = q / D4;
    int d4 = q - t * D4;
    const float4* yp = (const float4*)g_ypair;
    float4 a = yp[(size_t)(2 * t) * D4 + d4];
    float4 b = yp[(size_t)(2 * t + 1) * D4 + d4];
    float4 o;
    o.x = a.x + b.x; o.y = a.y + b.y; o.z = a.z + b.z; o.w = a.w + b.w;
    ((float4*)out)[q] = o;
}

// ---------------------------------------------------------------------------
extern "C" void kernel_launch(void* const* d_in, const int* in_sizes, int n_in,
                              void* d_out, int out_size) {
    const float* x    = (const float*)d_in[0];
    const float* ep   = (const float*)d_in[1];
    const int*   eidx = (const int*)  d_in[2];
    const float* W1   = (const float*)d_in[3];
    const float* W2   = (const float*)d_in[4];
    float*       out  = (float*)d_out;

    cudaFuncSetAttribute(gemm1_mma, cudaFuncAttributeMaxDynamicSharedMemorySize, SMEM_DYN);
    cudaFuncSetAttribute(gemm2_mma, cudaFuncAttributeMaxDynamicSharedMemorySize, SMEM_DYN);

    bucket_kernel<<<1, 512>>>(eidx);
    conv_x_kernel<<<NTOK, 256>>>(x);

    int w1_4 = E_NUM * D_DIM * H2 / 4;
    conv_w1_kernel<<<(w1_4 + 255) / 256, 256>>>(W1);
    int w2_4 = E_NUM * H_DIM * D_DIM / 4;
    conv_w2_kernel<<<(w2_4 + 255) / 256, 256>>>(W2);

    dim3 g1(H_DIM / 64, NPAIR / 128, E_NUM);    // (16, 32, 8)
    gemm1_mma<<<g1, 256, SMEM_DYN>>>();

    dim3 g2(D_DIM / 128, NPAIR / 128, E_NUM);   // (8, 32, 8)
    gemm2_mma<<<g2, 256, SMEM_DYN>>>(ep);

    int total4 = NTOK * (D_DIM / 4);
    combine_kernel<<<(total4 + 255) / 256, 256>>>(out);
}

// round 7
// speedup vs baseline: 3.1820x; 1.3137x over previous
#include <cuda_runtime.h>
#include <cuda_fp16.h>
#include <cstdint>
#include <math.h>

#define E_NUM 8
#define D_DIM 1024
#define H_DIM 1024
#define H2    2048
#define NTOK  2048
#define NPAIR 4096

// ----------------------------- scratch globals ------------------------------
__device__ int g_pairs[NPAIR];
__device__ int g_cnt[E_NUM];
__device__ int g_off[E_NUM];
__device__ __half g_x[(size_t)NTOK * D_DIM];                // by TOKEN
__device__ __half g_w1_hi[(size_t)E_NUM * D_DIM * H2];      // [E][k=D][n=2H]
__device__ __half g_w2_hi[(size_t)E_NUM * H_DIM * D_DIM];   // [E][k=H][n=D]
__device__ __half g_act[(size_t)NPAIR * H_DIM];             // by sorted SLOT
__device__ float g_ypair[(size_t)NPAIR * D_DIM];            // by pair id

// ------------------------------ helpers -------------------------------------
__device__ __forceinline__ uint32_t smem_u32(const void* p) {
    uint32_t a;
    asm("{ .reg .u64 t; cvta.to.shared.u64 t, %1; cvt.u32.u64 %0, t; }"
        : "=r"(a) : "l"(p));
    return a;
}
__device__ __forceinline__ void cp16(uint32_t dst, const void* src) {
    asm volatile("cp.async.cg.shared.global [%0], [%1], 16;"
                 :: "r"(dst), "l"(src) : "memory");
}
#define CP_COMMIT() asm volatile("cp.async.commit_group;" ::: "memory")
#define CP_WAIT(n)  asm volatile("cp.async.wait_group %0;" :: "n"(n) : "memory")

__device__ __forceinline__ void ldsm4(uint32_t* r, uint32_t a) {
    asm volatile("ldmatrix.sync.aligned.m8n8.x4.shared.b16 {%0,%1,%2,%3}, [%4];"
                 : "=r"(r[0]), "=r"(r[1]), "=r"(r[2]), "=r"(r[3]) : "r"(a));
}
__device__ __forceinline__ void ldsm4t(uint32_t* r, uint32_t a) {
    asm volatile("ldmatrix.sync.aligned.m8n8.x4.trans.shared.b16 {%0,%1,%2,%3}, [%4];"
                 : "=r"(r[0]), "=r"(r[1]), "=r"(r[2]), "=r"(r[3]) : "r"(a));
}
__device__ __forceinline__ void mma16816(float* d, const uint32_t* a, const uint32_t* b) {
    asm volatile(
        "mma.sync.aligned.m16n8k16.row.col.f32.f16.f16.f32 "
        "{%0,%1,%2,%3}, {%4,%5,%6,%7}, {%8,%9}, {%0,%1,%2,%3};"
        : "+f"(d[0]), "+f"(d[1]), "+f"(d[2]), "+f"(d[3])
        : "r"(a[0]), "r"(a[1]), "r"(a[2]), "r"(a[3]), "r"(b[0]), "r"(b[1]));
}
__device__ __forceinline__ uint32_t pack_h2(__half a, __half b) {
    return ((uint32_t)__half_as_ushort(b) << 16) | (uint32_t)__half_as_ushort(a);
}
__device__ __forceinline__ float silu_mul(float h, float g) {
    return h * (g / (1.f + __expf(-g)));
}

// SMEM: rows_s[128] ints @0; stages @512.
// Stage: A [128m][32k] pitch 80 | B [32k][128n] pitch 272.  3 stages.
#define A_PITCH  80
#define B_PITCH  272
#define OFF_A    0
#define OFF_B    (128 * A_PITCH)
#define STAGE_SZ (128 * A_PITCH + 32 * B_PITCH)     // 18944
#define NSTAGE   3
#define SMEM_DYN (512 + NSTAGE * STAGE_SZ)          // 57344

// ---------------------------------------------------------------------------
// Kernel 0: bucket pairs by expert (single CTA)
// ---------------------------------------------------------------------------
__global__ void bucket_kernel(const int* __restrict__ expert_idxs) {
    __shared__ int scnt[E_NUM];
    __shared__ int soff[E_NUM];
    __shared__ int spos[E_NUM];
    int tid = threadIdx.x;
    if (tid < E_NUM) scnt[tid] = 0;
    __syncthreads();
    for (int i = tid; i < NPAIR; i += blockDim.x)
        atomicAdd(&scnt[expert_idxs[i]], 1);
    __syncthreads();
    if (tid == 0) {
        int s = 0;
        for (int e = 0; e < E_NUM; e++) { soff[e] = s; spos[e] = s; s += scnt[e]; }
    }
    __syncthreads();
    for (int i = tid; i < NPAIR; i += blockDim.x) {
        int e = expert_idxs[i];
        int pos = atomicAdd(&spos[e], 1);
        g_pairs[pos] = i;
    }
    __syncthreads();
    if (tid < E_NUM) { g_cnt[tid] = scnt[tid]; g_off[tid] = soff[tid]; }
}

// ---------------------------------------------------------------------------
// Kernel 1: convert x by TOKEN to fp16
// ---------------------------------------------------------------------------
__global__ void conv_x_kernel(const float* __restrict__ x) {
    int tok = blockIdx.x;
    int t   = threadIdx.x;
    float4 v = ((const float4*)(x + (size_t)tok * D_DIM))[t];
    size_t o = (size_t)tok * D_DIM + t * 4;
    *(uint2*)(g_x + o) = make_uint2(
        pack_h2(__float2half_rn(v.x), __float2half_rn(v.y)),
        pack_h2(__float2half_rn(v.z), __float2half_rn(v.w)));
}

// ---------------------------------------------------------------------------
// Kernel 2a/2b: streaming convert W1/W2 fp32 -> fp16 (device-global dst)
// ---------------------------------------------------------------------------
__global__ void conv_w1_kernel(const float* __restrict__ W1) {
    const int total4 = E_NUM * D_DIM * H2 / 4;
    int idx = blockIdx.x * blockDim.x + threadIdx.x;
    if (idx >= total4) return;
    float4 v = ((const float4*)W1)[idx];
    uint2 o;
    o.x = pack_h2(__float2half_rn(v.x), __float2half_rn(v.y));
    o.y = pack_h2(__float2half_rn(v.z), __float2half_rn(v.w));
    *(uint2*)(g_w1_hi + (size_t)idx * 4) = o;
}

__global__ void conv_w2_kernel(const float* __restrict__ W2) {
    const int total4 = E_NUM * H_DIM * D_DIM / 4;
    int idx = blockIdx.x * blockDim.x + threadIdx.x;
    if (idx >= total4) return;
    float4 v = ((const float4*)W2)[idx];
    uint2 o;
    o.x = pack_h2(__float2half_rn(v.x), __float2half_rn(v.y));
    o.y = pack_h2(__float2half_rn(v.z), __float2half_rn(v.w));
    *(uint2*)(g_w2_hi + (size_t)idx * 4) = o;
}

// ---------------------------------------------------------------------------
// GEMM1 (mma.sync fp16 single-pass): act = h * silu(g)
//   CTA 128 rows x (64 h + 64 g cols). 8 warps = wm(4) x wc(2); warp 32m x 64c.
//   grid = (H/64, NPAIR/128, E)
// ---------------------------------------------------------------------------
__global__ void __launch_bounds__(256, 1) gemm1_mma() {
    extern __shared__ char smem[];
    const int e   = blockIdx.z;
    const int bn  = blockIdx.x;
    const int bm  = blockIdx.y;
    const int cnt = g_cnt[e];
    if (bm * 128 >= cnt) return;
    const int off = g_off[e];
    const int tid = threadIdx.x;
    const int wid = tid >> 5;
    const int l   = tid & 31;
    const int wm  = wid >> 1;
    const int wc  = wid & 1;

    int* rows_s = (int*)smem;
    const uint32_t sbase = smem_u32(smem) + 512;

    if (tid < 128) {
        int m = bm * 128 + tid;
        rows_s[tid] = (m < cnt) ? (g_pairs[off + m] >> 1) : 0;
    }
    __syncthreads();

    uint32_t a_rel[2][2];
#pragma unroll
    for (int mt = 0; mt < 2; mt++)
#pragma unroll
        for (int kk = 0; kk < 2; kk++)
            a_rel[mt][kk] = (wm * 32 + mt * 16 + (l & 15)) * A_PITCH + kk * 32 + (l >> 4) * 16;

    uint32_t b_rel[4][2];
#pragma unroll
    for (int p = 0; p < 4; p++) {
        int colbase = (p < 2) ? (wc * 32 + p * 16) : (64 + wc * 32 + (p - 2) * 16);
#pragma unroll
        for (int kk = 0; kk < 2; kk++)
            b_rel[p][kk] = (kk * 16 + (l & 15)) * B_PITCH + (colbase + (l >> 4) * 8) * 2;
    }

    float acc[2][8][4];
#pragma unroll
    for (int mt = 0; mt < 2; mt++)
#pragma unroll
        for (int nt = 0; nt < 8; nt++)
#pragma unroll
            for (int i = 0; i < 4; i++) acc[mt][nt][i] = 0.f;

    auto load_stage = [&](int c, int buf) {
        const int kt = c * 32;
        const uint32_t st = sbase + buf * STAGE_SZ;
        // A: 512 chunks of 16B
#pragma unroll
        for (int i = 0; i < 2; i++) {
            int q = tid + i * 256;
            int r = q >> 2, ch = q & 3;
            cp16(st + OFF_A + r * A_PITCH + ch * 16,
                 g_x + (size_t)rows_s[r] * D_DIM + kt + ch * 8);
        }
        // B: 512 chunks; cols 0-63 h @ bn*64, 64-127 g @ H+bn*64
#pragma unroll
        for (int i = 0; i < 2; i++) {
            int q = tid + i * 256;
            int r = q >> 4, ch = q & 15;
            int gcol = (ch < 8) ? (bn * 64 + ch * 8) : (H_DIM + bn * 64 + (ch - 8) * 8);
            cp16(st + OFF_B + r * B_PITCH + ch * 16,
                 g_w1_hi + ((size_t)e * D_DIM + kt + r) * H2 + gcol);
        }
        CP_COMMIT();
    };

    load_stage(0, 0);
    load_stage(1, 1);

    for (int c = 0; c < 32; c++) {
        const int buf = c % NSTAGE;
        if (c < 30) { load_stage(c + 2, (c + 2) % NSTAGE); CP_WAIT(2); }
        else if (c == 30) { CP_WAIT(1); }
        else { CP_WAIT(0); }
        __syncthreads();
        const uint32_t st = sbase + buf * STAGE_SZ;
#pragma unroll
        for (int kk = 0; kk < 2; kk++) {
            uint32_t ah[2][4], bf[4][4];
#pragma unroll
            for (int mt = 0; mt < 2; mt++)
                ldsm4(ah[mt], st + OFF_A + a_rel[mt][kk]);
#pragma unroll
            for (int p = 0; p < 4; p++)
                ldsm4t(bf[p], st + OFF_B + b_rel[p][kk]);
#pragma unroll
            for (int mt = 0; mt < 2; mt++)
#pragma unroll
                for (int nt = 0; nt < 8; nt++)
                    mma16816(acc[mt][nt], ah[mt], &bf[nt >> 1][(nt & 1) * 2]);
        }
        __syncthreads();
    }

    // ---- epilogue: pair h (nt) with g (nt+4), SiLU-GLU, store fp16 ----
#pragma unroll
    for (int mt = 0; mt < 2; mt++) {
        int m0 = bm * 128 + wm * 32 + mt * 16 + (l >> 2);
        int m1 = m0 + 8;
        bool v0 = (m0 < cnt), v1 = (m1 < cnt);
        size_t row0 = (size_t)(off + m0) * H_DIM;
        size_t row1 = (size_t)(off + m1) * H_DIM;
#pragma unroll
        for (int nt = 0; nt < 4; nt++) {
            int col = bn * 64 + wc * 32 + nt * 8 + 2 * (l & 3);
            float a0 = silu_mul(acc[mt][nt][0], acc[mt][nt + 4][0]);
            float a1 = silu_mul(acc[mt][nt][1], acc[mt][nt + 4][1]);
            float a2 = silu_mul(acc[mt][nt][2], acc[mt][nt + 4][2]);
            float a3 = silu_mul(acc[mt][nt][3], acc[mt][nt + 4][3]);
            if (v0)
                *(uint32_t*)(g_act + row0 + col) =
                    pack_h2(__float2half_rn(a0), __float2half_rn(a1));
            if (v1)
                *(uint32_t*)(g_act + row1 + col) =
                    pack_h2(__float2half_rn(a2), __float2half_rn(a3));
        }
    }
}

// ---------------------------------------------------------------------------
// GEMM2 (mma.sync fp16 single-pass): y_pair = (act @ W2) * p, scatter
//   CTA 128 x 128, warp 32m x 64n.  grid = (D/128, NPAIR/128, E)
// ---------------------------------------------------------------------------
__global__ void __launch_bounds__(256, 1) gemm2_mma(const float* __restrict__ expert_p) {
    extern __shared__ char smem[];
    const int e   = blockIdx.z;
    const int bn  = blockIdx.x;
    const int bm  = blockIdx.y;
    const int cnt = g_cnt[e];
    if (bm * 128 >= cnt) return;
    const int off = g_off[e];
    const int tid = threadIdx.x;
    const int wid = tid >> 5;
    const int l   = tid & 31;
    const int wm  = wid >> 1;
    const int wc  = wid & 1;

    const uint32_t sbase = smem_u32(smem) + 512;

    uint32_t a_rel[2][2], b_rel[4][2];
#pragma unroll
    for (int mt = 0; mt < 2; mt++)
#pragma unroll
        for (int kk = 0; kk < 2; kk++)
            a_rel[mt][kk] = (wm * 32 + mt * 16 + (l & 15)) * A_PITCH + kk * 32 + (l >> 4) * 16;
#pragma unroll
    for (int p = 0; p < 4; p++) {
        int colbase = wc * 64 + p * 16;
#pragma unroll
        for (int kk = 0; kk < 2; kk++)
            b_rel[p][kk] = (kk * 16 + (l & 15)) * B_PITCH + (colbase + (l >> 4) * 8) * 2;
    }

    float acc[2][8][4];
#pragma unroll
    for (int mt = 0; mt < 2; mt++)
#pragma unroll
        for (int nt = 0; nt < 8; nt++)
#pragma unroll
            for (int i = 0; i < 4; i++) acc[mt][nt][i] = 0.f;

    auto load_stage = [&](int c, int buf) {
        const int kt = c * 32;
        const uint32_t st = sbase + buf * STAGE_SZ;
#pragma unroll
        for (int i = 0; i < 2; i++) {
            int q = tid + i * 256;
            int r = q >> 2, ch = q & 3;
            int gr = off + bm * 128 + r;
            if (gr > NPAIR - 1) gr = NPAIR - 1;
            cp16(st + OFF_A + r * A_PITCH + ch * 16,
                 g_act + (size_t)gr * H_DIM + kt + ch * 8);
        }
#pragma unroll
        for (int i = 0; i < 2; i++) {
            int q = tid + i * 256;
            int r = q >> 4, ch = q & 15;
            cp16(st + OFF_B + r * B_PITCH + ch * 16,
                 g_w2_hi + ((size_t)e * H_DIM + kt + r) * D_DIM + bn * 128 + ch * 8);
        }
        CP_COMMIT();
    };

    load_stage(0, 0);
    load_stage(1, 1);

    for (int c = 0; c < 32; c++) {
        const int buf = c % NSTAGE;
        if (c < 30) { load_stage(c + 2, (c + 2) % NSTAGE); CP_WAIT(2); }
        else if (c == 30) { CP_WAIT(1); }
        else { CP_WAIT(0); }
        __syncthreads();
        const uint32_t st = sbase + buf * STAGE_SZ;
#pragma unroll
        for (int kk = 0; kk < 2; kk++) {
            uint32_t ah[2][4], bf[4][4];
#pragma unroll
            for (int mt = 0; mt < 2; mt++)
                ldsm4(ah[mt], st + OFF_A + a_rel[mt][kk]);
#pragma unroll
            for (int p = 0; p < 4; p++)
                ldsm4t(bf[p], st + OFF_B + b_rel[p][kk]);
#pragma unroll
            for (int mt = 0; mt < 2; mt++)
#pragma unroll
                for (int nt = 0; nt < 8; nt++)
                    mma16816(acc[mt][nt], ah[mt], &bf[nt >> 1][(nt & 1) * 2]);
        }
        __syncthreads();
    }

    // ---- epilogue: scale by gate prob, scatter rows by pair id ----
#pragma unroll
    for (int mt = 0; mt < 2; mt++) {
        int m0 = bm * 128 + wm * 32 + mt * 16 + (l >> 2);
        int m1 = m0 + 8;
        bool v0 = (m0 < cnt), v1 = (m1 < cnt);
        int   pid0 = 0, pid1 = 0;
        float pv0 = 0.f, pv1 = 0.f;
        if (v0) { pid0 = g_pairs[off + m0]; pv0 = expert_p[pid0]; }
        if (v1) { pid1 = g_pairs[off + m1]; pv1 = expert_p[pid1]; }
        float* dst0 = g_ypair + (size_t)pid0 * D_DIM;
        float* dst1 = g_ypair + (size_t)pid1 * D_DIM;
#pragma unroll
        for (int nt = 0; nt < 8; nt++) {
            int col = bn * 128 + wc * 64 + nt * 8 + 2 * (l & 3);
            if (v0) {
                float2 o = make_float2(acc[mt][nt][0] * pv0, acc[mt][nt][1] * pv0);
                *(float2*)(dst0 + col) = o;
            }
            if (v1) {
                float2 o = make_float2(acc[mt][nt][2] * pv1, acc[mt][nt][3] * pv1);
                *(float2*)(dst1 + col) = o;
            }
        }
    }
}

// ---------------------------------------------------------------------------
// Kernel 5: combine the K=2 slots of each token
// ---------------------------------------------------------------------------
__global__ void combine_kernel(float* __restrict__ out) {
    const int D4 = D_DIM / 4;
    int q = blockIdx.x * blockDim.x + threadIdx.x;
    if (q >= NTOK * D4) return;
    int t  = q / D4;
    int d4 = q - t * D4;
    const float4* yp = (const float4*)g_ypair;
    float4 a = yp[(size_t)(2 * t) * D4 + d4];
    float4 b = yp[(size_t)(2 * t + 1) * D4 + d4];
    float4 o;
    o.x = a.x + b.x; o.y = a.y + b.y; o.z = a.z + b.z; o.w = a.w + b.w;
    ((float4*)out)[q] = o;
}

// ---------------------------------------------------------------------------
extern "C" void kernel_launch(void* const* d_in, const int* in_sizes, int n_in,
                              void* d_out, int out_size) {
    const float* x    = (const float*)d_in[0];
    const float* ep   = (const float*)d_in[1];
    const int*   eidx = (const int*)  d_in[2];
    const float* W1   = (const float*)d_in[3];
    const float* W2   = (const float*)d_in[4];
    float*       out  = (float*)d_out;

    cudaFuncSetAttribute(gemm1_mma, cudaFuncAttributeMaxDynamicSharedMemorySize, SMEM_DYN);
    cudaFuncSetAttribute(gemm2_mma, cudaFuncAttributeMaxDynamicSharedMemorySize, SMEM_DYN);

    bucket_kernel<<<1, 512>>>(eidx);
    conv_x_kernel<<<NTOK, 256>>>(x);

    int w1_4 = E_NUM * D_DIM * H2 / 4;
    conv_w1_kernel<<<(w1_4 + 255) / 256, 256>>>(W1);
    int w2_4 = E_NUM * H_DIM * D_DIM / 4;
    conv_w2_kernel<<<(w2_4 + 255) / 256, 256>>>(W2);

    dim3 g1(H_DIM / 64, NPAIR / 128, E_NUM);    // (16, 32, 8)
    gemm1_mma<<<g1, 256, SMEM_DYN>>>();

    dim3 g2(D_DIM / 128, NPAIR / 128, E_NUM);   // (8, 32, 8)
    gemm2_mma<<<g2, 256, SMEM_DYN>>>(ep);

    int total4 = NTOK * (D_DIM / 4);
    combine_kernel<<<(total4 + 255) / 256, 256>>>(out);
}